// round 8
// baseline (speedup 1.0000x reference)
#include <cuda_runtime.h>
#include <math.h>

#define BB 64
#define SS 512
#define HH 1024
#define LL 64
#define NM (BB * SS)          // 32768 rows
#define NEM (NM * LL)         // 2097152

__device__ float g_part[2 * NEM];   // split-K partial sums
__device__ float g_llh[BB];

// ---- f32x2 helpers -------------------------------------------------------
union F4U { float4 v; float f[4]; unsigned long long u[2]; };

__device__ __forceinline__ void ffma2(unsigned long long& d,
                                      unsigned long long a,
                                      unsigned long long b) {
    asm("fma.rn.f32x2 %0, %1, %2, %0;" : "+l"(d) : "l"(a), "l"(b));
}
__device__ __forceinline__ unsigned long long dup2(float a) {
    unsigned long long d;
    asm("mov.b64 %0, {%1, %1};" : "=l"(d) : "r"(__float_as_uint(a)));
    return d;
}
__device__ __forceinline__ float lo2(unsigned long long x) {
    return __uint_as_float((unsigned)(x & 0xffffffffull));
}
__device__ __forceinline__ float hi2(unsigned long long x) {
    return __uint_as_float((unsigned)(x >> 32));
}
__device__ __forceinline__ unsigned long long pack2(float a, float b) {
    return (unsigned long long)__float_as_uint(a) |
           ((unsigned long long)__float_as_uint(b) << 32);
}

// ---------------------------------------------------------------------------
// GEMM split-K=2: R6 inner loop (tile 128x64, 128 thr, 8x8 micro, FFMA2/N).
// grid 512: blockIdx = mtile*2 + ksplit. Partials (no bias) -> g_part.
// ---------------------------------------------------------------------------
#define ASTR 132

__global__ __launch_bounds__(128) void gemm_kernel(
    const float* __restrict__ hs, const float* __restrict__ W,
    float* __restrict__ part)
{
    __shared__ __align__(16) float As[32 * ASTR];
    __shared__ __align__(16) float Bs[32 * 64];

    const int tid = threadIdx.x;
    const int tc = tid & 7;
    const int tr = tid >> 3;
    const int m0 = (blockIdx.x >> 1) * 128;
    const int ks = blockIdx.x & 1;
    const int kbase = ks * (HH / 2);

    unsigned long long acc[8][4];
#pragma unroll
    for (int r = 0; r < 8; r++)
#pragma unroll
        for (int c = 0; c < 4; c++) acc[r][c] = 0ull;

    for (int k0 = kbase; k0 < kbase + HH / 2; k0 += 32) {
        __syncthreads();
#pragma unroll
        for (int p = 0; p < 8; p++) {
            int q = tid + p * 128;
            int row = q >> 3;
            int kq = q & 7;
            float4 v = *(const float4*)&hs[(size_t)(m0 + row) * HH + k0 + kq * 4];
            As[(kq * 4 + 0) * ASTR + row] = v.x;
            As[(kq * 4 + 1) * ASTR + row] = v.y;
            As[(kq * 4 + 2) * ASTR + row] = v.z;
            As[(kq * 4 + 3) * ASTR + row] = v.w;
        }
#pragma unroll
        for (int p = 0; p < 4; p++) {
            int idx = tid + p * 128;
            int r = idx >> 4;
            int c4 = idx & 15;
            float4 v = *(const float4*)&W[(size_t)(k0 + r) * LL + c4 * 4];
            *(float4*)&Bs[r * 64 + c4 * 4] = v;
        }
        __syncthreads();

#pragma unroll 4
        for (int k = 0; k < 32; k++) {
            F4U b0, b1, a0, a1;
            b0.v = *(const float4*)&Bs[k * 64 + tc * 8];
            b1.v = *(const float4*)&Bs[k * 64 + tc * 8 + 4];
            a0.v = *(const float4*)&As[k * ASTR + tr * 8];
            a1.v = *(const float4*)&As[k * ASTR + tr * 8 + 4];
#pragma unroll
            for (int r = 0; r < 4; r++) {
                unsigned long long ad = dup2(a0.f[r]);
                ffma2(acc[r][0], ad, b0.u[0]);
                ffma2(acc[r][1], ad, b0.u[1]);
                ffma2(acc[r][2], ad, b1.u[0]);
                ffma2(acc[r][3], ad, b1.u[1]);
            }
#pragma unroll
            for (int r = 0; r < 4; r++) {
                unsigned long long ad = dup2(a1.f[r]);
                ffma2(acc[r + 4][0], ad, b0.u[0]);
                ffma2(acc[r + 4][1], ad, b0.u[1]);
                ffma2(acc[r + 4][2], ad, b1.u[0]);
                ffma2(acc[r + 4][3], ad, b1.u[1]);
            }
        }
    }

    float* dst = part + (size_t)ks * NEM;
#pragma unroll
    for (int r = 0; r < 8; r++) {
        size_t base = (size_t)(m0 + tr * 8 + r) * LL + tc * 8;
        float4 v0, v1;
        v0.x = lo2(acc[r][0]); v0.y = hi2(acc[r][0]);
        v0.z = lo2(acc[r][1]); v0.w = hi2(acc[r][1]);
        v1.x = lo2(acc[r][2]); v1.y = hi2(acc[r][2]);
        v1.z = lo2(acc[r][3]); v1.w = hi2(acc[r][3]);
        *(float4*)&dst[base] = v0;
        *(float4*)&dst[base + 4] = v1;
    }
}

// ---------------------------------------------------------------------------
// finish: em = part0 + part1 + bias -> out_em (scalar stores: 4B alignment)
// ---------------------------------------------------------------------------
__global__ __launch_bounds__(256) void finish_kernel(
    const float* __restrict__ part, const float* __restrict__ bias,
    float* __restrict__ out_em)
{
    int i0 = (blockIdx.x * 256 + threadIdx.x) * 8;   // grid covers NEM
    float4 a0 = *(const float4*)&part[i0];
    float4 a1 = *(const float4*)&part[i0 + 4];
    float4 b0 = *(const float4*)&part[NEM + i0];
    float4 b1 = *(const float4*)&part[NEM + i0 + 4];
    int bi = i0 & 63;
    out_em[i0 + 0] = a0.x + b0.x + bias[bi + 0];
    out_em[i0 + 1] = a0.y + b0.y + bias[bi + 1];
    out_em[i0 + 2] = a0.z + b0.z + bias[bi + 2];
    out_em[i0 + 3] = a0.w + b0.w + bias[bi + 3];
    out_em[i0 + 4] = a1.x + b1.x + bias[bi + 4];
    out_em[i0 + 5] = a1.y + b1.y + bias[bi + 5];
    out_em[i0 + 6] = a1.z + b1.z + bias[bi + 6];
    out_em[i0 + 7] = a1.w + b1.w + bias[bi + 7];
}

// ---------------------------------------------------------------------------
// CRF: 1 warp per sequence, 2 states per thread (j, j+32).
// Linear-space scan, renorm by w_0 every 8 steps, em prefetched 2 steps
// ahead in registers (L2-hot), exp on consumption, double-buffered u_sh,
// ONE __syncwarp per step.
// ---------------------------------------------------------------------------
__device__ __forceinline__ int tag_of(int x) {
    int t = (x == -100) ? 0 : x;
    return max(0, min(LL - 1, t));
}

__global__ __launch_bounds__(32) void crf_kernel(
    const float* __restrict__ em_all,   // = d_out + 1
    const int* __restrict__ mask,
    const int* __restrict__ labels,
    const float* __restrict__ start_t,
    const float* __restrict__ end_t,
    const float* __restrict__ trans)
{
    const int b = blockIdx.x;
    const int l = threadIdx.x;          // 0..31
    const int j = l, j2 = l + 32;

    const float* em = em_all + (size_t)b * (SS * LL);
    const int* msk = mask + b * SS;
    const int* lab = labels + (size_t)b * SS;

    __shared__ __align__(16) float u_sh[2][64];

    // ---- length (warp reduce) ----
    int cnt = 0;
    for (int t = l; t < SS; t += 32) cnt += msk[t];
#pragma unroll
    for (int o = 16; o > 0; o >>= 1) cnt += __shfl_xor_sync(0xffffffffu, cnt, o);
    const int len = max(1, min(SS, cnt));

    // ---- numerator (warp reduce; all lanes end with same value) ----
    float nsum = 0.f;
    for (int t = 1 + l; t < len; t += 32) {
        int tp = tag_of(lab[t - 1]);
        int tc = tag_of(lab[t]);
        nsum += trans[tp * LL + tc] + em[t * LL + tc];
    }
#pragma unroll
    for (int o = 16; o > 0; o >>= 1) nsum += __shfl_xor_sync(0xffffffffu, nsum, o);
    int t0 = tag_of(lab[0]);
    int tl = tag_of(lab[len - 1]);
    const float numerator = start_t[t0] + em[t0] + nsum + end_t[tl];

    // ---- P pairs over i for both owned states ----
    unsigned long long P2a[32], P2b[32];
#pragma unroll
    for (int q = 0; q < 32; q++) {
        P2a[q] = pack2(__expf(trans[(2 * q) * LL + j]),
                       __expf(trans[(2 * q + 1) * LL + j]));
        P2b[q] = pack2(__expf(trans[(2 * q) * LL + j2]),
                       __expf(trans[(2 * q + 1) * LL + j2]));
    }

    // ---- init ----
    float wj = __expf(start_t[j] + em[j]);
    float wk = __expf(start_t[j2] + em[j2]);
    u_sh[0][j] = wj;
    u_sh[0][j2] = wk;
    float logshift = 0.f;

    // register prefetch pipeline: A = em(t), B = em(t+1)
    float emA_j = 0.f, emA_k = 0.f, emB_j = 0.f, emB_k = 0.f;
    if (len > 1) { emA_j = em[LL + j]; emA_k = em[LL + j2]; }
    if (len > 2) { emB_j = em[2 * LL + j]; emB_k = em[2 * LL + j2]; }
    __syncwarp();

    for (int t = 1; t < len; t++) {
        float ej = __expf(emA_j);
        float ek = __expf(emA_k);
        emA_j = emB_j; emA_k = emB_k;
        if (t + 2 < len) {
            emB_j = em[(size_t)(t + 2) * LL + j];
            emB_k = em[(size_t)(t + 2) * LL + j2];
        }

        const float* U = u_sh[(t - 1) & 1];
        float u0 = U[0];

        unsigned long long a0 = 0ull, a1 = 0ull, a2 = 0ull, a3 = 0ull;
        unsigned long long c0 = 0ull, c1 = 0ull, c2 = 0ull, c3 = 0ull;
#pragma unroll
        for (int q = 0; q < 8; q++) {       // 16 quads -> 2 per iter
            F4U ua, ub;
            ua.v = *(const float4*)&U[q * 8];
            ub.v = *(const float4*)&U[q * 8 + 4];
            ffma2(a0, ua.u[0], P2a[4 * q + 0]);
            ffma2(a1, ua.u[1], P2a[4 * q + 1]);
            ffma2(a2, ub.u[0], P2a[4 * q + 2]);
            ffma2(a3, ub.u[1], P2a[4 * q + 3]);
            ffma2(c0, ua.u[0], P2b[4 * q + 0]);
            ffma2(c1, ua.u[1], P2b[4 * q + 1]);
            ffma2(c2, ub.u[0], P2b[4 * q + 2]);
            ffma2(c3, ub.u[1], P2b[4 * q + 3]);
        }
        float rj = ((lo2(a0) + hi2(a0)) + (lo2(a1) + hi2(a1))) +
                   ((lo2(a2) + hi2(a2)) + (lo2(a3) + hi2(a3)));
        float rk = ((lo2(c0) + hi2(c0)) + (lo2(c1) + hi2(c1))) +
                   ((lo2(c2) + hi2(c2)) + (lo2(c3) + hi2(c3)));
        wj = rj * ej;
        wk = rk * ek;
        if ((t & 7) == 0) {
            float ri = __frcp_rn(u0);
            wj *= ri;
            wk *= ri;
            logshift += __logf(u0);
        }
        u_sh[t & 1][j] = wj;
        u_sh[t & 1][j2] = wk;
        __syncwarp();
    }

    // ---- log Z ----
    float val = wj * __expf(end_t[j]) + wk * __expf(end_t[j2]);
#pragma unroll
    for (int o = 16; o > 0; o >>= 1) val += __shfl_xor_sync(0xffffffffu, val, o);
    if (l == 0) {
        float log_z = __logf(val) + logshift;
        g_llh[b] = numerator - log_z;
    }
}

// ---------------------------------------------------------------------------
__global__ void loss_kernel(float* __restrict__ out) {
    int t = threadIdx.x;   // 32 threads
    float v = g_llh[t] + g_llh[t + 32];
#pragma unroll
    for (int o = 16; o > 0; o >>= 1) v += __shfl_down_sync(0xffffffffu, v, o);
    if (t == 0) out[0] = -v * (1.0f / BB);
}

// ---------------------------------------------------------------------------
extern "C" void kernel_launch(void* const* d_in, const int* in_sizes, int n_in,
                              void* d_out, int out_size)
{
    const float* hs      = (const float*)d_in[0];
    const int* mask      = (const int*)d_in[1];
    const int* labels    = (const int*)d_in[2];
    const float* W       = (const float*)d_in[3];
    const float* bias    = (const float*)d_in[4];
    const float* start_t = (const float*)d_in[5];
    const float* end_t   = (const float*)d_in[6];
    const float* trans   = (const float*)d_in[7];
    float* out = (float*)d_out;    // out[0]=loss, out[1..]=emissions

    float* part = nullptr;
    cudaGetSymbolAddress((void**)&part, g_part);

    gemm_kernel<<<512, 128>>>(hs, W, part);
    finish_kernel<<<NEM / (256 * 8), 256>>>(part, bias, out + 1);
    crf_kernel<<<BB, 32>>>(out + 1, mask, labels, start_t, end_t, trans);
    loss_kernel<<<1, 32>>>(out);
}

// round 9
// speedup vs baseline: 1.2999x; 1.2999x over previous
#include <cuda_runtime.h>
#include <math.h>

#define BB 64
#define SS 512
#define HH 1024
#define LL 64
#define NEM (BB * SS * LL)

__device__ float g_E[NEM];    // exp(emissions)
__device__ float g_llh[BB];

// ---- f32x2 helpers -------------------------------------------------------
union F4U { float4 v; float f[4]; unsigned long long u[2]; };

__device__ __forceinline__ void ffma2(unsigned long long& d,
                                      unsigned long long a,
                                      unsigned long long b) {
    asm("fma.rn.f32x2 %0, %1, %2, %0;" : "+l"(d) : "l"(a), "l"(b));
}
__device__ __forceinline__ unsigned long long dup2(float a) {
    unsigned long long d;
    asm("mov.b64 %0, {%1, %1};" : "=l"(d) : "r"(__float_as_uint(a)));
    return d;
}
__device__ __forceinline__ float lo2(unsigned long long x) {
    return __uint_as_float((unsigned)(x & 0xffffffffull));
}
__device__ __forceinline__ float hi2(unsigned long long x) {
    return __uint_as_float((unsigned)(x >> 32));
}
__device__ __forceinline__ unsigned long long pack2(float a, float b) {
    return (unsigned long long)__float_as_uint(a) |
           ((unsigned long long)__float_as_uint(b) << 32);
}

// ---------------------------------------------------------------------------
// GEMM: em[m][l] = sum_h hs[m][h]*W[h][l] + b[l]
// Tile 64x64, 64 threads, 8x8 micro-tile (R6 inner loop), K-tile 32,
// grid 512 -> ~3.5 blocks/SM wave-1 with room for 8 resident.
// ---------------------------------------------------------------------------
#define ASTR 68

__global__ __launch_bounds__(64, 8) void gemm_kernel(
    const float* __restrict__ hs, const float* __restrict__ W,
    const float* __restrict__ bias,
    float* __restrict__ out_em, float* __restrict__ Eo)
{
    __shared__ __align__(16) float As[32 * ASTR];   // [k][m], m padded to 68
    __shared__ __align__(16) float Bs[32 * 64];     // [k][n]

    const int tid = threadIdx.x;
    const int tc = tid & 7;     // col group: cols tc*8 .. +7
    const int tr = tid >> 3;    // row group: rows tr*8 .. +7
    const int m0 = blockIdx.x * 64;

    unsigned long long acc[8][4];
#pragma unroll
    for (int r = 0; r < 8; r++)
#pragma unroll
        for (int c = 0; c < 4; c++) acc[r][c] = 0ull;

    for (int k0 = 0; k0 < HH; k0 += 32) {
        __syncthreads();
        // A tile: 64 m x 32 k, transposed into As[k][m]  (512 quads)
#pragma unroll
        for (int p = 0; p < 8; p++) {
            int q = tid + p * 64;
            int row = q >> 3;               // m 0..63
            int kq = q & 7;                 // k-quad 0..7
            float4 v = *(const float4*)&hs[(size_t)(m0 + row) * HH + k0 + kq * 4];
            As[(kq * 4 + 0) * ASTR + row] = v.x;
            As[(kq * 4 + 1) * ASTR + row] = v.y;
            As[(kq * 4 + 2) * ASTR + row] = v.z;
            As[(kq * 4 + 3) * ASTR + row] = v.w;
        }
        // B tile: 32 k x 64 n, row-major (512 quads)
#pragma unroll
        for (int p = 0; p < 8; p++) {
            int idx = tid + p * 64;
            int r = idx >> 4;               // k 0..31
            int c4 = idx & 15;              // col quad
            float4 v = *(const float4*)&W[(size_t)(k0 + r) * LL + c4 * 4];
            *(float4*)&Bs[r * 64 + c4 * 4] = v;
        }
        __syncthreads();

#pragma unroll 4
        for (int k = 0; k < 32; k++) {
            F4U b0, b1, a0, a1;
            b0.v = *(const float4*)&Bs[k * 64 + tc * 8];
            b1.v = *(const float4*)&Bs[k * 64 + tc * 8 + 4];
            a0.v = *(const float4*)&As[k * ASTR + tr * 8];
            a1.v = *(const float4*)&As[k * ASTR + tr * 8 + 4];
#pragma unroll
            for (int r = 0; r < 4; r++) {
                unsigned long long ad = dup2(a0.f[r]);
                ffma2(acc[r][0], ad, b0.u[0]);
                ffma2(acc[r][1], ad, b0.u[1]);
                ffma2(acc[r][2], ad, b1.u[0]);
                ffma2(acc[r][3], ad, b1.u[1]);
            }
#pragma unroll
            for (int r = 0; r < 4; r++) {
                unsigned long long ad = dup2(a1.f[r]);
                ffma2(acc[r + 4][0], ad, b0.u[0]);
                ffma2(acc[r + 4][1], ad, b0.u[1]);
                ffma2(acc[r + 4][2], ad, b1.u[0]);
                ffma2(acc[r + 4][3], ad, b1.u[1]);
            }
        }
    }

    float bj[8];
#pragma unroll
    for (int c = 0; c < 8; c++) bj[c] = bias[tc * 8 + c];
#pragma unroll
    for (int r = 0; r < 8; r++) {
        size_t base = (size_t)(m0 + tr * 8 + r) * LL + tc * 8;
#pragma unroll
        for (int c = 0; c < 4; c++) {
            float e0 = lo2(acc[r][c]) + bj[2 * c + 0];
            float e1 = hi2(acc[r][c]) + bj[2 * c + 1];
            out_em[base + 2 * c + 0] = e0;
            out_em[base + 2 * c + 1] = e1;
            Eo[base + 2 * c + 0] = expf(e0);
            Eo[base + 2 * c + 1] = expf(e1);
        }
    }
}

// ---------------------------------------------------------------------------
// CRF (R6 version, measured ~97us): 64 blocks x 64 threads, linear-space
// scan with P=exp(trans) in registers, renorm every 8 steps, E double-
// buffered in smem.
// ---------------------------------------------------------------------------
__device__ __forceinline__ int tag_of(int x) {
    int t = (x == -100) ? 0 : x;
    return max(0, min(LL - 1, t));
}

__global__ __launch_bounds__(64) void crf_kernel(
    const float* __restrict__ em_all,   // raw emissions (= d_out+1)
    const float* __restrict__ E_all,    // g_E
    const int* __restrict__ mask,
    const int* __restrict__ labels,
    const float* __restrict__ start_t,
    const float* __restrict__ end_t,
    const float* __restrict__ trans)
{
    const int b = blockIdx.x;
    const int j = threadIdx.x;           // 0..63

    const float* em = em_all + (size_t)b * (SS * LL);
    const float* Ee = E_all + (size_t)b * (SS * LL);
    const int* msk = mask + b * SS;
    const int* lab = labels + (size_t)b * SS;

    __shared__ __align__(16) float4 u_sh[2][16];
    __shared__ __align__(16) float4 Esm[2][512];
    __shared__ float red[64];
    __shared__ int len_sh;
    __shared__ float num_sh;

    // ---- sequence length (contiguous prefix mask) ----
    int cnt = 0;
    for (int t = j; t < SS; t += 64) cnt += msk[t];
    red[j] = (float)cnt;
    __syncthreads();
#pragma unroll
    for (int s = 32; s > 0; s >>= 1) {
        if (j < s) red[j] += red[j + s];
        __syncthreads();
    }
    if (j == 0) len_sh = max(1, min(SS, (int)(red[0] + 0.5f)));
    __syncthreads();
    const int len = len_sh;

    // ---- numerator ----
    float nsum = 0.f;
    for (int t = 1 + j; t < len; t += 64) {
        int tp = tag_of(lab[t - 1]);
        int tc = tag_of(lab[t]);
        nsum += trans[tp * LL + tc] + em[t * LL + tc];
    }
    __syncthreads();
    red[j] = nsum;
    __syncthreads();
#pragma unroll
    for (int s = 32; s > 0; s >>= 1) {
        if (j < s) red[j] += red[j + s];
        __syncthreads();
    }
    if (j == 0) {
        int t0 = tag_of(lab[0]);
        int tl = tag_of(lab[len - 1]);
        num_sh = start_t[t0] + em[t0] + red[0] + end_t[tl];
    }

    // ---- P2[q] = (exp(trans[2q][j]), exp(trans[2q+1][j])) ----
    unsigned long long P2[32];
#pragma unroll
    for (int q = 0; q < 32; q++)
        P2[q] = pack2(__expf(trans[(2 * q) * LL + j]),
                      __expf(trans[(2 * q + 1) * LL + j]));

    // ---- E chunk 0 ----
#pragma unroll
    for (int p = 0; p < 8; p++) {
        int idx = p * 64 + j;
        Esm[0][idx] = *(const float4*)&Ee[(size_t)idx * 4];
    }
    __syncthreads();

    float w = __expf(start_t[j]) * ((const float*)Esm[0])[j];
    ((float*)u_sh[0])[j] = w;
    float logshift = 0.f;

    const int nchunks = (len + 31) >> 5;
    for (int ch = 0; ch < nchunks; ch++) {
        if (ch + 1 < nchunks) {
            int t0n = (ch + 1) << 5;
            int nq = min(512, (len - t0n) * 16);
#pragma unroll
            for (int p = 0; p < 8; p++) {
                int idx = p * 64 + j;
                if (idx < nq)
                    Esm[(ch + 1) & 1][idx] =
                        *(const float4*)&Ee[(size_t)t0n * 64 + (size_t)idx * 4];
            }
        }
        const float* Ep = (const float*)Esm[ch & 1];
        int tA = (ch == 0) ? 1 : (ch << 5);
        int tB = min(len, (ch + 1) << 5);

        for (int t = tA; t < tB; t++) {
            __syncthreads();
            const float4* U = u_sh[(t - 1) & 1];
            float u0 = ((const float*)U)[0];

            unsigned long long a0 = 0ull, a1 = 0ull, a2 = 0ull, a3 = 0ull;
#pragma unroll
            for (int q4 = 0; q4 < 16; q4 += 2) {
                F4U ua, ub;
                ua.v = U[q4];
                ub.v = U[q4 + 1];
                ffma2(a0, ua.u[0], P2[2 * q4 + 0]);
                ffma2(a1, ua.u[1], P2[2 * q4 + 1]);
                ffma2(a2, ub.u[0], P2[2 * q4 + 2]);
                ffma2(a3, ub.u[1], P2[2 * q4 + 3]);
            }
            float r = (lo2(a0) + hi2(a0)) + (lo2(a1) + hi2(a1)) +
                      (lo2(a2) + hi2(a2)) + (lo2(a3) + hi2(a3));
            float e = Ep[((t & 31) << 6) + j];
            float wn = r * e;
            if ((t & 7) == 0) {
                wn *= __frcp_rn(u0);
                logshift += __logf(u0);
            }
            w = wn;
            ((float*)u_sh[t & 1])[j] = w;
        }
        __syncthreads();
    }

    // ---- log Z ----
    red[j] = w * __expf(end_t[j]);
    __syncthreads();
#pragma unroll
    for (int s = 32; s > 0; s >>= 1) {
        if (j < s) red[j] += red[j + s];
        __syncthreads();
    }
    if (j == 0) {
        float log_z = __logf(red[0]) + logshift;
        g_llh[b] = num_sh - log_z;
    }
}

// ---------------------------------------------------------------------------
__global__ void loss_kernel(float* __restrict__ out) {
    int t = threadIdx.x;   // 32 threads
    float v = g_llh[t] + g_llh[t + 32];
#pragma unroll
    for (int o = 16; o > 0; o >>= 1) v += __shfl_down_sync(0xffffffffu, v, o);
    if (t == 0) out[0] = -v * (1.0f / BB);
}

// ---------------------------------------------------------------------------
extern "C" void kernel_launch(void* const* d_in, const int* in_sizes, int n_in,
                              void* d_out, int out_size)
{
    const float* hs      = (const float*)d_in[0];   // [B,S,H] f32
    const int* mask      = (const int*)d_in[1];     // [B,S]   i32
    const int* labels    = (const int*)d_in[2];     // [B,S]   i32
    const float* W       = (const float*)d_in[3];   // [H,L]   f32
    const float* bias    = (const float*)d_in[4];   // [L]
    const float* start_t = (const float*)d_in[5];   // [L]
    const float* end_t   = (const float*)d_in[6];   // [L]
    const float* trans   = (const float*)d_in[7];   // [L,L]
    float* out = (float*)d_out;    // out[0]=loss, out[1..]=emissions

    float* E_scratch = nullptr;
    cudaGetSymbolAddress((void**)&E_scratch, g_E);

    gemm_kernel<<<512, 64>>>(hs, W, bias, out + 1, E_scratch);
    crf_kernel<<<BB, 64>>>(out + 1, E_scratch, mask, labels,
                           start_t, end_t, trans);
    loss_kernel<<<1, 32>>>(out);
}

// round 10
// speedup vs baseline: 1.3676x; 1.0521x over previous
#include <cuda_runtime.h>
#include <math.h>

#define BB 64
#define SS 512
#define HH 1024
#define LL 64
#define NEM (BB * SS * LL)

__device__ float g_part[2 * NEM];   // split-K partials
__device__ float g_E[NEM];          // exp(emissions)
__device__ float g_llh[BB];

// ---- f32x2 helpers -------------------------------------------------------
union F4U { float4 v; float f[4]; unsigned long long u[2]; };

__device__ __forceinline__ void ffma2(unsigned long long& d,
                                      unsigned long long a,
                                      unsigned long long b) {
    asm("fma.rn.f32x2 %0, %1, %2, %0;" : "+l"(d) : "l"(a), "l"(b));
}
__device__ __forceinline__ unsigned long long dup2(float a) {
    unsigned long long d;
    asm("mov.b64 %0, {%1, %1};" : "=l"(d) : "r"(__float_as_uint(a)));
    return d;
}
__device__ __forceinline__ float lo2(unsigned long long x) {
    return __uint_as_float((unsigned)(x & 0xffffffffull));
}
__device__ __forceinline__ float hi2(unsigned long long x) {
    return __uint_as_float((unsigned)(x >> 32));
}
__device__ __forceinline__ unsigned long long pack2(float a, float b) {
    return (unsigned long long)__float_as_uint(a) |
           ((unsigned long long)__float_as_uint(b) << 32);
}

// ---------------------------------------------------------------------------
// GEMM split-K=2: tile 64x64, 64 threads, 8x8 micro (R9 inner loop).
// grid 1024 = 512 m-tiles x 2 k-halves -> ~14 warps/SM.
// No max-blocks cap: let ptxas use regs to pipeline k+1 loads under k FMAs.
// ---------------------------------------------------------------------------
#define ASTR 68

__global__ __launch_bounds__(64) void gemm_kernel(
    const float* __restrict__ hs, const float* __restrict__ W,
    float* __restrict__ part)
{
    __shared__ __align__(16) float As[32 * ASTR];   // [k][m], padded
    __shared__ __align__(16) float Bs[32 * 64];     // [k][n]

    const int tid = threadIdx.x;
    const int tc = tid & 7;
    const int tr = tid >> 3;
    const int m0 = (blockIdx.x >> 1) * 64;
    const int ks = blockIdx.x & 1;
    const int kbase = ks * (HH / 2);

    unsigned long long acc[8][4];
#pragma unroll
    for (int r = 0; r < 8; r++)
#pragma unroll
        for (int c = 0; c < 4; c++) acc[r][c] = 0ull;

    for (int k0 = kbase; k0 < kbase + HH / 2; k0 += 32) {
        __syncthreads();
        // A tile: 64 m x 32 k, transposed into As[k][m]
#pragma unroll
        for (int p = 0; p < 8; p++) {
            int q = tid + p * 64;
            int row = q >> 3;
            int kq = q & 7;
            float4 v = *(const float4*)&hs[(size_t)(m0 + row) * HH + k0 + kq * 4];
            As[(kq * 4 + 0) * ASTR + row] = v.x;
            As[(kq * 4 + 1) * ASTR + row] = v.y;
            As[(kq * 4 + 2) * ASTR + row] = v.z;
            As[(kq * 4 + 3) * ASTR + row] = v.w;
        }
        // B tile: 32 k x 64 n
#pragma unroll
        for (int p = 0; p < 8; p++) {
            int idx = tid + p * 64;
            int r = idx >> 4;
            int c4 = idx & 15;
            float4 v = *(const float4*)&W[(size_t)(k0 + r) * LL + c4 * 4];
            *(float4*)&Bs[r * 64 + c4 * 4] = v;
        }
        __syncthreads();

#pragma unroll 4
        for (int k = 0; k < 32; k++) {
            F4U b0, b1, a0, a1;
            b0.v = *(const float4*)&Bs[k * 64 + tc * 8];
            b1.v = *(const float4*)&Bs[k * 64 + tc * 8 + 4];
            a0.v = *(const float4*)&As[k * ASTR + tr * 8];
            a1.v = *(const float4*)&As[k * ASTR + tr * 8 + 4];
#pragma unroll
            for (int r = 0; r < 4; r++) {
                unsigned long long ad = dup2(a0.f[r]);
                ffma2(acc[r][0], ad, b0.u[0]);
                ffma2(acc[r][1], ad, b0.u[1]);
                ffma2(acc[r][2], ad, b1.u[0]);
                ffma2(acc[r][3], ad, b1.u[1]);
            }
#pragma unroll
            for (int r = 0; r < 4; r++) {
                unsigned long long ad = dup2(a1.f[r]);
                ffma2(acc[r + 4][0], ad, b0.u[0]);
                ffma2(acc[r + 4][1], ad, b0.u[1]);
                ffma2(acc[r + 4][2], ad, b1.u[0]);
                ffma2(acc[r + 4][3], ad, b1.u[1]);
            }
        }
    }

    float* dst = part + (size_t)ks * NEM;
#pragma unroll
    for (int r = 0; r < 8; r++) {
        size_t base = (size_t)(m0 + tr * 8 + r) * LL + tc * 8;
        float4 v0, v1;
        v0.x = lo2(acc[r][0]); v0.y = hi2(acc[r][0]);
        v0.z = lo2(acc[r][1]); v0.w = hi2(acc[r][1]);
        v1.x = lo2(acc[r][2]); v1.y = hi2(acc[r][2]);
        v1.z = lo2(acc[r][3]); v1.w = hi2(acc[r][3]);
        *(float4*)&dst[base] = v0;
        *(float4*)&dst[base + 4] = v1;
    }
}

// ---------------------------------------------------------------------------
// finish: em = p0 + p1 + bias -> out_em (4B-aligned, scalar stores) and
// E = exp(em) -> g_E (16B-aligned, vector stores).
// ---------------------------------------------------------------------------
__global__ __launch_bounds__(256) void finish_kernel(
    const float* __restrict__ part, const float* __restrict__ bias,
    float* __restrict__ out_em, float* __restrict__ Eo)
{
    int i0 = (blockIdx.x * 256 + threadIdx.x) * 8;
    float4 a0 = *(const float4*)&part[i0];
    float4 a1 = *(const float4*)&part[i0 + 4];
    float4 b0 = *(const float4*)&part[NEM + i0];
    float4 b1 = *(const float4*)&part[NEM + i0 + 4];
    int bi = i0 & 63;
    float e0 = a0.x + b0.x + bias[bi + 0];
    float e1 = a0.y + b0.y + bias[bi + 1];
    float e2 = a0.z + b0.z + bias[bi + 2];
    float e3 = a0.w + b0.w + bias[bi + 3];
    float e4 = a1.x + b1.x + bias[bi + 4];
    float e5 = a1.y + b1.y + bias[bi + 5];
    float e6 = a1.z + b1.z + bias[bi + 6];
    float e7 = a1.w + b1.w + bias[bi + 7];
    out_em[i0 + 0] = e0; out_em[i0 + 1] = e1;
    out_em[i0 + 2] = e2; out_em[i0 + 3] = e3;
    out_em[i0 + 4] = e4; out_em[i0 + 5] = e5;
    out_em[i0 + 6] = e6; out_em[i0 + 7] = e7;
    float4 x0 = make_float4(expf(e0), expf(e1), expf(e2), expf(e3));
    float4 x1 = make_float4(expf(e4), expf(e5), expf(e6), expf(e7));
    *(float4*)&Eo[i0] = x0;
    *(float4*)&Eo[i0 + 4] = x1;
}

// ---------------------------------------------------------------------------
// CRF (R9, measured-good): 64 blocks x 64 threads, linear-space scan,
// P=exp(trans) in regs, renorm every 8 steps, E double-buffered in smem.
// ---------------------------------------------------------------------------
__device__ __forceinline__ int tag_of(int x) {
    int t = (x == -100) ? 0 : x;
    return max(0, min(LL - 1, t));
}

__global__ __launch_bounds__(64) void crf_kernel(
    const float* __restrict__ em_all,   // = d_out + 1
    const float* __restrict__ E_all,    // g_E
    const int* __restrict__ mask,
    const int* __restrict__ labels,
    const float* __restrict__ start_t,
    const float* __restrict__ end_t,
    const float* __restrict__ trans)
{
    const int b = blockIdx.x;
    const int j = threadIdx.x;

    const float* em = em_all + (size_t)b * (SS * LL);
    const float* Ee = E_all + (size_t)b * (SS * LL);
    const int* msk = mask + b * SS;
    const int* lab = labels + (size_t)b * SS;

    __shared__ __align__(16) float4 u_sh[2][16];
    __shared__ __align__(16) float4 Esm[2][512];
    __shared__ float red[64];
    __shared__ int len_sh;
    __shared__ float num_sh;

    int cnt = 0;
    for (int t = j; t < SS; t += 64) cnt += msk[t];
    red[j] = (float)cnt;
    __syncthreads();
#pragma unroll
    for (int s = 32; s > 0; s >>= 1) {
        if (j < s) red[j] += red[j + s];
        __syncthreads();
    }
    if (j == 0) len_sh = max(1, min(SS, (int)(red[0] + 0.5f)));
    __syncthreads();
    const int len = len_sh;

    float nsum = 0.f;
    for (int t = 1 + j; t < len; t += 64) {
        int tp = tag_of(lab[t - 1]);
        int tc = tag_of(lab[t]);
        nsum += trans[tp * LL + tc] + em[t * LL + tc];
    }
    __syncthreads();
    red[j] = nsum;
    __syncthreads();
#pragma unroll
    for (int s = 32; s > 0; s >>= 1) {
        if (j < s) red[j] += red[j + s];
        __syncthreads();
    }
    if (j == 0) {
        int t0 = tag_of(lab[0]);
        int tl = tag_of(lab[len - 1]);
        num_sh = start_t[t0] + em[t0] + red[0] + end_t[tl];
    }

    unsigned long long P2[32];
#pragma unroll
    for (int q = 0; q < 32; q++)
        P2[q] = pack2(__expf(trans[(2 * q) * LL + j]),
                      __expf(trans[(2 * q + 1) * LL + j]));

#pragma unroll
    for (int p = 0; p < 8; p++) {
        int idx = p * 64 + j;
        Esm[0][idx] = *(const float4*)&Ee[(size_t)idx * 4];
    }
    __syncthreads();

    float w = __expf(start_t[j]) * ((const float*)Esm[0])[j];
    ((float*)u_sh[0])[j] = w;
    float logshift = 0.f;

    const int nchunks = (len + 31) >> 5;
    for (int ch = 0; ch < nchunks; ch++) {
        if (ch + 1 < nchunks) {
            int t0n = (ch + 1) << 5;
            int nq = min(512, (len - t0n) * 16);
#pragma unroll
            for (int p = 0; p < 8; p++) {
                int idx = p * 64 + j;
                if (idx < nq)
                    Esm[(ch + 1) & 1][idx] =
                        *(const float4*)&Ee[(size_t)t0n * 64 + (size_t)idx * 4];
            }
        }
        const float* Ep = (const float*)Esm[ch & 1];
        int tA = (ch == 0) ? 1 : (ch << 5);
        int tB = min(len, (ch + 1) << 5);

        for (int t = tA; t < tB; t++) {
            __syncthreads();
            const float4* U = u_sh[(t - 1) & 1];
            float u0 = ((const float*)U)[0];

            unsigned long long a0 = 0ull, a1 = 0ull, a2 = 0ull, a3 = 0ull;
#pragma unroll
            for (int q4 = 0; q4 < 16; q4 += 2) {
                F4U ua, ub;
                ua.v = U[q4];
                ub.v = U[q4 + 1];
                ffma2(a0, ua.u[0], P2[2 * q4 + 0]);
                ffma2(a1, ua.u[1], P2[2 * q4 + 1]);
                ffma2(a2, ub.u[0], P2[2 * q4 + 2]);
                ffma2(a3, ub.u[1], P2[2 * q4 + 3]);
            }
            float r = (lo2(a0) + hi2(a0)) + (lo2(a1) + hi2(a1)) +
                      (lo2(a2) + hi2(a2)) + (lo2(a3) + hi2(a3));
            float e = Ep[((t & 31) << 6) + j];
            float wn = r * e;
            if ((t & 7) == 0) {
                wn *= __frcp_rn(u0);
                logshift += __logf(u0);
            }
            w = wn;
            ((float*)u_sh[t & 1])[j] = w;
        }
        __syncthreads();
    }

    red[j] = w * __expf(end_t[j]);
    __syncthreads();
#pragma unroll
    for (int s = 32; s > 0; s >>= 1) {
        if (j < s) red[j] += red[j + s];
        __syncthreads();
    }
    if (j == 0) {
        float log_z = __logf(red[0]) + logshift;
        g_llh[b] = num_sh - log_z;
    }
}

// ---------------------------------------------------------------------------
__global__ void loss_kernel(float* __restrict__ out) {
    int t = threadIdx.x;
    float v = g_llh[t] + g_llh[t + 32];
#pragma unroll
    for (int o = 16; o > 0; o >>= 1) v += __shfl_down_sync(0xffffffffu, v, o);
    if (t == 0) out[0] = -v * (1.0f / BB);
}

// ---------------------------------------------------------------------------
extern "C" void kernel_launch(void* const* d_in, const int* in_sizes, int n_in,
                              void* d_out, int out_size)
{
    const float* hs      = (const float*)d_in[0];
    const int* mask      = (const int*)d_in[1];
    const int* labels    = (const int*)d_in[2];
    const float* W       = (const float*)d_in[3];
    const float* bias    = (const float*)d_in[4];
    const float* start_t = (const float*)d_in[5];
    const float* end_t   = (const float*)d_in[6];
    const float* trans   = (const float*)d_in[7];
    float* out = (float*)d_out;    // out[0]=loss, out[1..]=emissions

    float* part = nullptr;
    float* E_scratch = nullptr;
    cudaGetSymbolAddress((void**)&part, g_part);
    cudaGetSymbolAddress((void**)&E_scratch, g_E);

    gemm_kernel<<<1024, 64>>>(hs, W, part);
    finish_kernel<<<NEM / (256 * 8), 256>>>(part, bias, out + 1, E_scratch);
    crf_kernel<<<BB, 64>>>(out + 1, E_scratch, mask, labels,
                           start_t, end_t, trans);
    loss_kernel<<<1, 32>>>(out);
}

// round 13
// speedup vs baseline: 1.8728x; 1.3694x over previous
#include <cuda_runtime.h>
#include <cuda_bf16.h>
#include <math.h>
#include <cstdint>

#define BB 64
#define SS 512
#define HH 1024
#define LL 64
#define NEM (BB * SS * LL)

__device__ float g_E[NEM];                    // exp(emissions)
__device__ float g_llh[BB];
__device__ __nv_bfloat16 g_Wth[LL * HH];      // W^T hi  [n][k]
__device__ __nv_bfloat16 g_Wtl[LL * HH];      // W^T lo  [n][k]

// ---------------------------------------------------------------------------
// mma.sync m16n8k16 bf16 (sm_80+; compiles for plain sm_100)
// ---------------------------------------------------------------------------
__device__ __forceinline__ void mma16816(float* c, const uint32_t* a,
                                         const uint32_t* b) {
    asm volatile(
        "mma.sync.aligned.m16n8k16.row.col.f32.bf16.bf16.f32 "
        "{%0,%1,%2,%3}, {%4,%5,%6,%7}, {%8,%9}, {%0,%1,%2,%3};\n"
        : "+f"(c[0]), "+f"(c[1]), "+f"(c[2]), "+f"(c[3])
        : "r"(a[0]), "r"(a[1]), "r"(a[2]), "r"(a[3]), "r"(b[0]), "r"(b[1]));
}

// pack (x -> low, y -> high) hi bf16x2 and residual-lo bf16x2
__device__ __forceinline__ void cvt_hilo(float x, float y,
                                         uint32_t& hi, uint32_t& lo) {
    uint32_t h;
    asm("cvt.rn.bf16x2.f32 %0, %1, %2;" : "=r"(h) : "f"(y), "f"(x));
    float xh = __uint_as_float((h & 0xffffu) << 16);
    float yh = __uint_as_float(h & 0xffff0000u);
    float xr = x - xh, yr = y - yh;
    asm("cvt.rn.bf16x2.f32 %0, %1, %2;" : "=r"(lo) : "f"(yr), "f"(xr));
    hi = h;
}

__device__ __forceinline__ unsigned short bfbits(float x) {
    __nv_bfloat16 h = __float2bfloat16_rn(x);
    return *reinterpret_cast<unsigned short*>(&h);
}
__device__ __forceinline__ float bf2f(unsigned short u) {
    __nv_bfloat16 h = *reinterpret_cast<__nv_bfloat16*>(&u);
    return __bfloat162float(h);
}

// ---------------------------------------------------------------------------
// prep: Wt_hi[n][k] = bf16(W[k][n]); Wt_lo = bf16(residual)
// ---------------------------------------------------------------------------
__global__ __launch_bounds__(256) void prep_kernel(const float* __restrict__ W) {
    int idx = blockIdx.x * 256 + threadIdx.x;     // 0 .. 65535
    int n = idx >> 10, k = idx & 1023;
    float v = W[k * LL + n];
    unsigned short h = bfbits(v);
    float r = v - bf2f(h);
    g_Wth[n * HH + k] = *reinterpret_cast<__nv_bfloat16*>(&h);
    unsigned short l = bfbits(r);
    g_Wtl[n * HH + k] = *reinterpret_cast<__nv_bfloat16*>(&l);
}

// ---------------------------------------------------------------------------
// GEMM via mma.sync: CTA = 128 thr (4 warps), m-tile 128 (32 rows/warp),
// N=64 (8 n-frags), K chunked by 128 (B hi/lo staged in smem, kpad=136).
// Per k16-step: A fp32 loaded per-fragment, hi/lo split in regs;
// D += Ahi*Bhi + Ahi*Blo + Alo*Bhi  (single fp32 accumulator set).
// ---------------------------------------------------------------------------
#define KPAD 136

__global__ __launch_bounds__(128) void gemm_kernel(
    const float* __restrict__ hs, const float* __restrict__ bias,
    float* __restrict__ out_em, float* __restrict__ Eo)
{
    __shared__ __align__(16) __nv_bfloat16 Bh_s[LL * KPAD];
    __shared__ __align__(16) __nv_bfloat16 Bl_s[LL * KPAD];

    const int tid = threadIdx.x;
    const int wid = tid >> 5;
    const int lane = tid & 31;
    const int gid = lane >> 2;      // groupID (row / col within frag)
    const int tig = lane & 3;       // thread-in-group
    const int m0 = blockIdx.x * 128;

    float acc[2][8][4];
#pragma unroll
    for (int mf = 0; mf < 2; mf++)
#pragma unroll
        for (int nf = 0; nf < 8; nf++)
#pragma unroll
            for (int i = 0; i < 4; i++) acc[mf][nf][i] = 0.f;

    for (int c = 0; c < 8; c++) {
        __syncthreads();
        // stage B chunk (hi+lo): 64n x 128k bf16 each
#pragma unroll
        for (int p = 0; p < 8; p++) {
            int idx = tid + p * 128;
            int n = idx >> 4, u = idx & 15;
            *(uint4*)((char*)Bh_s + n * (KPAD * 2) + u * 16) =
                *(const uint4*)((const char*)g_Wth + (size_t)n * 2048 + c * 256 + u * 16);
            *(uint4*)((char*)Bl_s + n * (KPAD * 2) + u * 16) =
                *(const uint4*)((const char*)g_Wtl + (size_t)n * 2048 + c * 256 + u * 16);
        }
        __syncthreads();

#pragma unroll
        for (int ks = 0; ks < 8; ks++) {
            const int k0 = c * 128 + ks * 16 + tig * 2;
            // ---- A fragments (fp32 -> hi/lo bf16x2 in regs) ----
            uint32_t ah[2][4], al[2][4];
#pragma unroll
            for (int mf = 0; mf < 2; mf++) {
                int r0 = m0 + wid * 32 + mf * 16 + gid;
                const float* base = hs + (size_t)r0 * HH;
                float2 v00 = *(const float2*)(base + k0);
                float2 v01 = *(const float2*)(base + k0 + 8);
                float2 v10 = *(const float2*)(base + 8 * HH + k0);
                float2 v11 = *(const float2*)(base + 8 * HH + k0 + 8);
                cvt_hilo(v00.x, v00.y, ah[mf][0], al[mf][0]);
                cvt_hilo(v10.x, v10.y, ah[mf][1], al[mf][1]);
                cvt_hilo(v01.x, v01.y, ah[mf][2], al[mf][2]);
                cvt_hilo(v11.x, v11.y, ah[mf][3], al[mf][3]);
            }
            // ---- B fragments from smem (conflict-free: kpad=136) ----
            uint32_t bh[8][2], bl[8][2];
            const int kk = ks * 16 + tig * 2;
#pragma unroll
            for (int nf = 0; nf < 8; nf++) {
                int n = nf * 8 + gid;
                int off0 = (n * KPAD + kk) * 2;
                bh[nf][0] = *(const uint32_t*)((const char*)Bh_s + off0);
                bh[nf][1] = *(const uint32_t*)((const char*)Bh_s + off0 + 16);
                bl[nf][0] = *(const uint32_t*)((const char*)Bl_s + off0);
                bl[nf][1] = *(const uint32_t*)((const char*)Bl_s + off0 + 16);
            }
            // ---- 48 HMMA ----
#pragma unroll
            for (int mf = 0; mf < 2; mf++)
#pragma unroll
                for (int nf = 0; nf < 8; nf++) {
                    mma16816(acc[mf][nf], ah[mf], bh[nf]);
                    mma16816(acc[mf][nf], ah[mf], bl[nf]);
                    mma16816(acc[mf][nf], al[mf], bh[nf]);
                }
        }
    }

    // ---- epilogue: frags -> bias -> em (scalar) + E=exp (float2) ----
#pragma unroll
    for (int mf = 0; mf < 2; mf++) {
        int r0 = m0 + wid * 32 + mf * 16 + gid;
#pragma unroll
        for (int nf = 0; nf < 8; nf++) {
            int col = nf * 8 + tig * 2;
            float b0v = bias[col], b1v = bias[col + 1];
            float e0 = acc[mf][nf][0] + b0v;
            float e1 = acc[mf][nf][1] + b1v;
            float e2 = acc[mf][nf][2] + b0v;
            float e3 = acc[mf][nf][3] + b1v;
            size_t p0 = (size_t)r0 * LL + col;
            size_t p1 = (size_t)(r0 + 8) * LL + col;
            out_em[p0] = e0; out_em[p0 + 1] = e1;
            out_em[p1] = e2; out_em[p1 + 1] = e3;
            *(float2*)&Eo[p0] = make_float2(__expf(e0), __expf(e1));
            *(float2*)&Eo[p1] = make_float2(__expf(e2), __expf(e3));
        }
    }
}

// ---------------------------------------------------------------------------
// CRF (R9/R10, measured-good): 64 blocks x 64 threads, linear-space scan.
// ---------------------------------------------------------------------------
union F4U { float4 v; float f[4]; unsigned long long u[2]; };
__device__ __forceinline__ void ffma2(unsigned long long& d,
                                      unsigned long long a, unsigned long long b) {
    asm("fma.rn.f32x2 %0, %1, %2, %0;" : "+l"(d) : "l"(a), "l"(b));
}
__device__ __forceinline__ float lo2(unsigned long long x) {
    return __uint_as_float((unsigned)(x & 0xffffffffull));
}
__device__ __forceinline__ float hi2(unsigned long long x) {
    return __uint_as_float((unsigned)(x >> 32));
}
__device__ __forceinline__ unsigned long long pack2(float a, float b) {
    return (unsigned long long)__float_as_uint(a) |
           ((unsigned long long)__float_as_uint(b) << 32);
}
__device__ __forceinline__ int tag_of(int x) {
    int t = (x == -100) ? 0 : x;
    return max(0, min(LL - 1, t));
}

__global__ __launch_bounds__(64) void crf_kernel(
    const float* __restrict__ em_all, const float* __restrict__ E_all,
    const int* __restrict__ mask, const int* __restrict__ labels,
    const float* __restrict__ start_t, const float* __restrict__ end_t,
    const float* __restrict__ trans)
{
    const int b = blockIdx.x;
    const int j = threadIdx.x;

    const float* em = em_all + (size_t)b * (SS * LL);
    const float* Ee = E_all + (size_t)b * (SS * LL);
    const int* msk = mask + b * SS;
    const int* lab = labels + (size_t)b * SS;

    __shared__ __align__(16) float4 u_sh[2][16];
    __shared__ __align__(16) float4 Esm[2][512];
    __shared__ float red[64];
    __shared__ int len_sh;
    __shared__ float num_sh;

    int cnt = 0;
    for (int t = j; t < SS; t += 64) cnt += msk[t];
    red[j] = (float)cnt;
    __syncthreads();
#pragma unroll
    for (int s = 32; s > 0; s >>= 1) {
        if (j < s) red[j] += red[j + s];
        __syncthreads();
    }
    if (j == 0) len_sh = max(1, min(SS, (int)(red[0] + 0.5f)));
    __syncthreads();
    const int len = len_sh;

    float nsum = 0.f;
    for (int t = 1 + j; t < len; t += 64) {
        int tp = tag_of(lab[t - 1]);
        int tc = tag_of(lab[t]);
        nsum += trans[tp * LL + tc] + em[t * LL + tc];
    }
    __syncthreads();
    red[j] = nsum;
    __syncthreads();
#pragma unroll
    for (int s = 32; s > 0; s >>= 1) {
        if (j < s) red[j] += red[j + s];
        __syncthreads();
    }
    if (j == 0) {
        int t0 = tag_of(lab[0]);
        int tl = tag_of(lab[len - 1]);
        num_sh = start_t[t0] + em[t0] + red[0] + end_t[tl];
    }

    unsigned long long P2[32];
#pragma unroll
    for (int q = 0; q < 32; q++)
        P2[q] = pack2(__expf(trans[(2 * q) * LL + j]),
                      __expf(trans[(2 * q + 1) * LL + j]));

#pragma unroll
    for (int p = 0; p < 8; p++) {
        int idx = p * 64 + j;
        Esm[0][idx] = *(const float4*)&Ee[(size_t)idx * 4];
    }
    __syncthreads();

    float w = __expf(start_t[j]) * ((const float*)Esm[0])[j];
    ((float*)u_sh[0])[j] = w;
    float logshift = 0.f;

    const int nchunks = (len + 31) >> 5;
    for (int ch = 0; ch < nchunks; ch++) {
        if (ch + 1 < nchunks) {
            int t0n = (ch + 1) << 5;
            int nq = min(512, (len - t0n) * 16);
#pragma unroll
            for (int p = 0; p < 8; p++) {
                int idx = p * 64 + j;
                if (idx < nq)
                    Esm[(ch + 1) & 1][idx] =
                        *(const float4*)&Ee[(size_t)t0n * 64 + (size_t)idx * 4];
            }
        }
        const float* Ep = (const float*)Esm[ch & 1];
        int tA = (ch == 0) ? 1 : (ch << 5);
        int tB = min(len, (ch + 1) << 5);

        for (int t = tA; t < tB; t++) {
            __syncthreads();
            const float4* U = u_sh[(t - 1) & 1];
            float u0 = ((const float*)U)[0];

            unsigned long long a0 = 0ull, a1 = 0ull, a2 = 0ull, a3 = 0ull;
#pragma unroll
            for (int q4 = 0; q4 < 16; q4 += 2) {
                F4U ua, ub;
                ua.v = U[q4];
                ub.v = U[q4 + 1];
                ffma2(a0, ua.u[0], P2[2 * q4 + 0]);
                ffma2(a1, ua.u[1], P2[2 * q4 + 1]);
                ffma2(a2, ub.u[0], P2[2 * q4 + 2]);
                ffma2(a3, ub.u[1], P2[2 * q4 + 3]);
            }
            float r = (lo2(a0) + hi2(a0)) + (lo2(a1) + hi2(a1)) +
                      (lo2(a2) + hi2(a2)) + (lo2(a3) + hi2(a3));
            float e = Ep[((t & 31) << 6) + j];
            float wn = r * e;
            if ((t & 7) == 0) {
                wn *= __frcp_rn(u0);
                logshift += __logf(u0);
            }
            w = wn;
            ((float*)u_sh[t & 1])[j] = w;
        }
        __syncthreads();
    }

    red[j] = w * __expf(end_t[j]);
    __syncthreads();
#pragma unroll
    for (int s = 32; s > 0; s >>= 1) {
        if (j < s) red[j] += red[j + s];
        __syncthreads();
    }
    if (j == 0) {
        float log_z = __logf(red[0]) + logshift;
        g_llh[b] = num_sh - log_z;
    }
}

// ---------------------------------------------------------------------------
__global__ void loss_kernel(float* __restrict__ out) {
    int t = threadIdx.x;
    float v = g_llh[t] + g_llh[t + 32];
#pragma unroll
    for (int o = 16; o > 0; o >>= 1) v += __shfl_down_sync(0xffffffffu, v, o);
    if (t == 0) out[0] = -v * (1.0f / BB);
}

// ---------------------------------------------------------------------------
extern "C" void kernel_launch(void* const* d_in, const int* in_sizes, int n_in,
                              void* d_out, int out_size)
{
    const float* hs      = (const float*)d_in[0];
    const int* mask      = (const int*)d_in[1];
    const int* labels    = (const int*)d_in[2];
    const float* W       = (const float*)d_in[3];
    const float* bias    = (const float*)d_in[4];
    const float* start_t = (const float*)d_in[5];
    const float* end_t   = (const float*)d_in[6];
    const float* trans   = (const float*)d_in[7];
    float* out = (float*)d_out;    // out[0]=loss, out[1..]=emissions

    float* E_scratch = nullptr;
    cudaGetSymbolAddress((void**)&E_scratch, g_E);

    prep_kernel<<<256, 256>>>(W);
    gemm_kernel<<<256, 128>>>(hs, bias, out + 1, E_scratch);
    crf_kernel<<<BB, 64>>>(out + 1, E_scratch, mask, labels,
                           start_t, end_t, trans);
    loss_kernel<<<1, 32>>>(out);
}